// round 13
// baseline (speedup 1.0000x reference)
#include <cuda_runtime.h>
#include <cuda_fp16.h>
#include <cstdint>
#include <cstddef>

#define L_SEQ 512
#define BATCH 128
#define DIM   128
#define HID   512
#define OUTD  5
#define N3H   1536
#define MROWS 65536  // L_SEQ*BATCH

// ---------------- scratch (static device globals; no allocations) ----------------
__device__ __align__(256) __half g_xh[MROWS * DIM];
__device__ __align__(256) __half g_W0t[N3H * DIM];
__device__ __align__(256) __half g_W1t[N3H * HID];
__device__ __align__(256) __half g_U[MROWS * N3H];
__device__ __align__(256) __half g_h1[MROWS * HID];
__device__ __align__(256) float  g_h2last[BATCH * HID];

// ---------------- helpers ----------------
__device__ __forceinline__ uint32_t smem_cast(const void* p)
{
    return (uint32_t)__cvta_generic_to_shared(p);
}

#define CP_ASYNC16(dst, src) asm volatile("cp.async.cg.shared.global [%0], [%1], 16;\n" :: "r"(dst), "l"(src))
#define CP_ASYNC4(dst, src)  asm volatile("cp.async.ca.shared.global [%0], [%1], 4;\n"  :: "r"(dst), "l"(src))
#define CP_COMMIT()          asm volatile("cp.async.commit_group;\n")
#define CP_WAIT1()           asm volatile("cp.async.wait_group 1;\n")
#define CP_WAIT14()          asm volatile("cp.async.wait_group 14;\n")

__device__ __forceinline__ float tanh_approx(float x)
{
    float t;
    asm("tanh.approx.f32 %0, %1;" : "=f"(t) : "f"(x));
    return t;
}

// ---------------- fused prep: x f2h + W0^T + W1^T (one launch) ----------------
// blocks [0, NB_F2H)                : x fp32 -> fp16 (float4/8 halfs per thread)
// blocks [NB_F2H, +NB_T0)           : W0 transpose+f2h  (48 x 4 tiles)
// blocks [NB_F2H+NB_T0, +NB_T1)     : W1 transpose+f2h  (48 x 16 tiles)
#define NB_F2H (MROWS * DIM / 4 / 256)   // 8192
#define NB_T0  ((N3H / 32) * (DIM / 32)) // 192
#define NB_T1  ((N3H / 32) * (HID / 32)) // 768

__device__ __forceinline__ void trans_tile(const float* __restrict__ W, __half* __restrict__ Wt,
                                           int K, int N, int bx, int by, int tid)
{
    __shared__ float tile[32][33];
    int tx = tid & 31;
    int ty = tid >> 5;        // 0..7
    int nb = bx * 32;
    int kb = by * 32;
#pragma unroll
    for (int j = 0; j < 32; j += 8)
        tile[ty + j][tx] = W[(size_t)(kb + ty + j) * N + (nb + tx)];
    __syncthreads();
#pragma unroll
    for (int j = 0; j < 32; j += 8)
        Wt[(size_t)(nb + ty + j) * K + (kb + tx)] = __float2half(tile[tx][ty + j]);
}

__global__ void prep_kernel(const float* __restrict__ x, __half* __restrict__ xh,
                            const float* __restrict__ W0, __half* __restrict__ w0t,
                            const float* __restrict__ W1, __half* __restrict__ w1t)
{
    int bid = blockIdx.x;
    int tid = threadIdx.x;
    if (bid < NB_F2H) {
        int i = bid * 256 + tid;
        float4 v = reinterpret_cast<const float4*>(x)[i];
        __half2 lo = __floats2half2_rn(v.x, v.y);
        __half2 hi = __floats2half2_rn(v.z, v.w);
        uint2 pkt;
        pkt.x = *reinterpret_cast<uint32_t*>(&lo);
        pkt.y = *reinterpret_cast<uint32_t*>(&hi);
        reinterpret_cast<uint2*>(xh)[i] = pkt;
    } else if (bid < NB_F2H + NB_T0) {
        int b = bid - NB_F2H;
        trans_tile(W0, w0t, DIM, N3H, b % (N3H / 32), b / (N3H / 32), tid);
    } else {
        int b = bid - NB_F2H - NB_T0;
        trans_tile(W1, w1t, HID, N3H, b % (N3H / 32), b / (N3H / 32), tid);
    }
}

// ---------------- common GEMM pieces ----------------
#define LDSM4(R0, R1, R2, R3, ADDR) \
    asm volatile("ldmatrix.sync.aligned.m8n8.x4.shared.b16 {%0,%1,%2,%3}, [%4];" \
                 : "=r"(R0), "=r"(R1), "=r"(R2), "=r"(R3) : "r"(ADDR))

#define MMA16816(C0, C1, C2, C3, A0, A1, A2, A3, B0, B1)                              \
    asm volatile("mma.sync.aligned.m16n8k16.row.col.f32.f16.f16.f32 "                  \
                 "{%0,%1,%2,%3}, {%4,%5,%6,%7}, {%8,%9}, {%0,%1,%2,%3};"               \
                 : "+f"(C0), "+f"(C1), "+f"(C2), "+f"(C3)                              \
                 : "r"(A0), "r"(A1), "r"(A2), "r"(A3), "r"(B0), "r"(B1))

__device__ __forceinline__ int sw_gran(int row, int seg)
{
    return ((row >> 1) << 3) | ((((row & 1) << 2) | seg) ^ ((row >> 1) & 7));
}

// epilogue bias: cols [0,HID) raw (scale 1, bias 0); cols >= HID scaled 0.5 + 0.5*b[n-HID]
// (tanh-form sigmoid pre-scaling; n-HID in [0,2H) spans bf then br, matching v layout)

// ---------------- GEMM standard: 128x128 tile, 256 thr, 3-stage (PROVEN) ----------------
__global__ void __launch_bounds__(256, 2) gemm_kernel(
    const __half* __restrict__ A,
    const __half* __restrict__ B,
    const float* __restrict__ braw,   // raw SRU bias [2H]
    __half* __restrict__ C,
    int K)
{
    __shared__ __align__(1024) __half As[3][128 * 32];
    __shared__ __align__(1024) __half Bs[3][128 * 32];

    const int tid  = threadIdx.x;
    const int lane = tid & 31;
    const int wid  = tid >> 5;
    const int wm   = wid & 3;
    const int wn   = wid >> 2;
    const int m0   = blockIdx.y * 128;
    const int n0   = blockIdx.x * 128;
    const bool gc  = (n0 >= HID);
    const float s  = gc ? 0.5f : 1.f;

    auto load_tile = [&](int buf, int k0) {
        uint32_t as = smem_cast(&As[buf][0]);
        uint32_t bs = smem_cast(&Bs[buf][0]);
#pragma unroll
        for (int i = 0; i < 2; i++) {
            int lin = tid + i * 256;
            int row = lin >> 2;
            int seg = lin & 3;
            int g   = sw_gran(row, seg);
            CP_ASYNC16(as + g * 16, A + (size_t)(m0 + row) * K + (k0 + seg * 8));
            CP_ASYNC16(bs + g * 16, B + (size_t)(n0 + row) * K + (k0 + seg * 8));
        }
    };

    float acc[2][8][4];
#pragma unroll
    for (int mi = 0; mi < 2; mi++)
#pragma unroll
        for (int ni = 0; ni < 8; ni++)
#pragma unroll
            for (int j = 0; j < 4; j++) acc[mi][ni][j] = 0.f;

    const int T = K >> 5;
    load_tile(0, 0);
    CP_COMMIT();
    load_tile(1, 32);
    CP_COMMIT();

    const int a_row_base = wm * 32 + (lane & 15);
    const int a_koff     = lane >> 4;
    const int b_row_base = wn * 64 + (lane & 7) + ((lane & 16) ? 8 : 0);
    const int b_koff     = (lane >> 3) & 1;

    for (int t = 0; t < T; t++) {
        CP_WAIT1();
        __syncthreads();

        if (t + 2 < T) load_tile((t + 2) % 3, (t + 2) << 5);
        CP_COMMIT();

        int cur = t % 3;
        uint32_t as = smem_cast(&As[cur][0]);
        uint32_t bs = smem_cast(&Bs[cur][0]);
#pragma unroll
        for (int kc = 0; kc < 2; kc++) {
            uint32_t a[2][4];
#pragma unroll
            for (int mi = 0; mi < 2; mi++) {
                int row = a_row_base + mi * 16;
                int seg = kc * 2 + a_koff;
                LDSM4(a[mi][0], a[mi][1], a[mi][2], a[mi][3], as + sw_gran(row, seg) * 16);
            }
            uint32_t bf[8][2];
#pragma unroll
            for (int nb = 0; nb < 4; nb++) {
                int row = b_row_base + nb * 16;
                int seg = kc * 2 + b_koff;
                LDSM4(bf[2 * nb][0], bf[2 * nb][1], bf[2 * nb + 1][0], bf[2 * nb + 1][1],
                      bs + sw_gran(row, seg) * 16);
            }
#pragma unroll
            for (int mi = 0; mi < 2; mi++)
#pragma unroll
                for (int ni = 0; ni < 8; ni++)
                    MMA16816(acc[mi][ni][0], acc[mi][ni][1], acc[mi][ni][2], acc[mi][ni][3],
                             a[mi][0], a[mi][1], a[mi][2], a[mi][3],
                             bf[ni][0], bf[ni][1]);
        }
        __syncthreads();
    }

#pragma unroll
    for (int mi = 0; mi < 2; mi++) {
        int m = m0 + wm * 32 + mi * 16 + (lane >> 2);
#pragma unroll
        for (int ni = 0; ni < 8; ni++) {
            int n = n0 + wn * 64 + ni * 8 + (lane & 3) * 2;
            float2 bb;
            if (gc) {
                bb = *reinterpret_cast<const float2*>(braw + (n - HID));
                bb.x *= 0.5f; bb.y *= 0.5f;
            } else {
                bb.x = 0.f; bb.y = 0.f;
            }
            __half2 lo = __floats2half2_rn(fmaf(acc[mi][ni][0], s, bb.x),
                                           fmaf(acc[mi][ni][1], s, bb.y));
            __half2 hi = __floats2half2_rn(fmaf(acc[mi][ni][2], s, bb.x),
                                           fmaf(acc[mi][ni][3], s, bb.y));
            *reinterpret_cast<__half2*>(C + (size_t)m * N3H + n)       = lo;
            *reinterpret_cast<__half2*>(C + (size_t)(m + 8) * N3H + n) = hi;
        }
    }
}

// ---------------- GEMM wide (layer 1, K=512): 128x256 tile, 512 thr, 3-stage ----------------
// Halves B re-reads: L2 fill traffic 1.6 GB -> 1.2 GB for the K=512 GEMM.
#define WA_STAGE 8192    // 128 rows x 32 halfs
#define WB_STAGE 16384   // 256 rows x 32 halfs
#define WB_BASE  (3 * WA_STAGE)
#define WSMEM_B  (3 * (WA_STAGE + WB_STAGE))   // 73728

__global__ void __launch_bounds__(512, 1) gemm_wide_kernel(
    const __half* __restrict__ A,
    const __half* __restrict__ B,
    const float* __restrict__ braw,
    __half* __restrict__ C,
    int K)
{
    extern __shared__ __align__(1024) char wsmem[];

    const int tid  = threadIdx.x;
    const int lane = tid & 31;
    const int wid  = tid >> 5;
    const int wm   = wid & 3;    // 4 warps along M (32 rows)
    const int wn   = wid >> 2;   // 4 warps along N (64 cols)
    const int m0   = blockIdx.y * 128;
    const int n0   = blockIdx.x * 256;
    const bool gc  = (n0 >= HID);     // HID % 256 == 0 -> uniform per CTA
    const float s  = gc ? 0.5f : 1.f;

    const uint32_t sb = smem_cast(wsmem);

    auto load_tile = [&](int buf, int k0) {
        uint32_t as = sb + buf * WA_STAGE;
        uint32_t bs = sb + WB_BASE + buf * WB_STAGE;
        {
            int row = tid >> 2;
            int seg = tid & 3;
            CP_ASYNC16(as + sw_gran(row, seg) * 16, A + (size_t)(m0 + row) * K + (k0 + seg * 8));
        }
#pragma unroll
        for (int i = 0; i < 2; i++) {
            int lin = tid + i * 512;
            int row = lin >> 2;
            int seg = lin & 3;
            CP_ASYNC16(bs + sw_gran(row, seg) * 16, B + (size_t)(n0 + row) * K + (k0 + seg * 8));
        }
    };

    float acc[2][8][4];
#pragma unroll
    for (int mi = 0; mi < 2; mi++)
#pragma unroll
        for (int ni = 0; ni < 8; ni++)
#pragma unroll
            for (int j = 0; j < 4; j++) acc[mi][ni][j] = 0.f;

    const int T = K >> 5;
    load_tile(0, 0);
    CP_COMMIT();
    load_tile(1, 32);
    CP_COMMIT();

    const int a_row_base = wm * 32 + (lane & 15);
    const int a_koff     = lane >> 4;
    const int b_row_base = wn * 64 + (lane & 7) + ((lane & 16) ? 8 : 0);
    const int b_koff     = (lane >> 3) & 1;

    for (int t = 0; t < T; t++) {
        CP_WAIT1();
        __syncthreads();

        if (t + 2 < T) load_tile((t + 2) % 3, (t + 2) << 5);
        CP_COMMIT();

        int cur = t % 3;
        uint32_t as = sb + cur * WA_STAGE;
        uint32_t bs = sb + WB_BASE + cur * WB_STAGE;
#pragma unroll
        for (int kc = 0; kc < 2; kc++) {
            uint32_t a[2][4];
#pragma unroll
            for (int mi = 0; mi < 2; mi++) {
                int row = a_row_base + mi * 16;
                int seg = kc * 2 + a_koff;
                LDSM4(a[mi][0], a[mi][1], a[mi][2], a[mi][3], as + sw_gran(row, seg) * 16);
            }
            uint32_t bf[8][2];
#pragma unroll
            for (int nb = 0; nb < 4; nb++) {
                int row = b_row_base + nb * 16;
                int seg = kc * 2 + b_koff;
                LDSM4(bf[2 * nb][0], bf[2 * nb][1], bf[2 * nb + 1][0], bf[2 * nb + 1][1],
                      bs + sw_gran(row, seg) * 16);
            }
#pragma unroll
            for (int mi = 0; mi < 2; mi++)
#pragma unroll
                for (int ni = 0; ni < 8; ni++)
                    MMA16816(acc[mi][ni][0], acc[mi][ni][1], acc[mi][ni][2], acc[mi][ni][3],
                             a[mi][0], a[mi][1], a[mi][2], a[mi][3],
                             bf[ni][0], bf[ni][1]);
        }
        __syncthreads();
    }

#pragma unroll
    for (int mi = 0; mi < 2; mi++) {
        int m = m0 + wm * 32 + mi * 16 + (lane >> 2);
#pragma unroll
        for (int ni = 0; ni < 8; ni++) {
            int n = n0 + wn * 64 + ni * 8 + (lane & 3) * 2;
            float2 bb;
            if (gc) {
                bb = *reinterpret_cast<const float2*>(braw + (n - HID));
                bb.x *= 0.5f; bb.y *= 0.5f;
            } else {
                bb.x = 0.f; bb.y = 0.f;
            }
            __half2 lo = __floats2half2_rn(fmaf(acc[mi][ni][0], s, bb.x),
                                           fmaf(acc[mi][ni][1], s, bb.y));
            __half2 hi = __floats2half2_rn(fmaf(acc[mi][ni][2], s, bb.x),
                                           fmaf(acc[mi][ni][3], s, bb.y));
            *reinterpret_cast<__half2*>(C + (size_t)m * N3H + n)       = lo;
            *reinterpret_cast<__half2*>(C + (size_t)(m + 8) * N3H + n) = hi;
        }
    }
}

// ---------------- SRU recurrence: per-thread cp.async ring, tanh sigmoid (PROVEN, DRAM-bound) ----------------
#define RSTAGES 16

__global__ void __launch_bounds__(32) sru_rec_kernel(
    const __half* __restrict__ U,    // u1/u2 cols pre-scaled 0.5 + 0.5*bias
    const float* __restrict__ v,
    __half* __restrict__ hout,
    float* __restrict__ hlast,
    int store_all)
{
    __shared__ __align__(128) __half2 sU[RSTAGES][3][32];   // 6 KB

    const int tid = threadIdx.x;
    const int b   = blockIdx.x >> 3;
    const int sub = blockIdx.x & 7;
    const int hp  = sub * 32 + tid;
    const int h   = hp << 1;

    float2 vf = *reinterpret_cast<const float2*>(v + h);
    float2 vr = *reinterpret_cast<const float2*>(v + HID + h);
    vf.x *= 0.5f; vf.y *= 0.5f;
    vr.x *= 0.5f; vr.y *= 0.5f;

    const char* src = (const char*)(U + (size_t)b * N3H + h);
    const size_t step_bytes = (size_t)BATCH * N3H * 2;
    const uint32_t smem0 = smem_cast(&sU[0][0][tid]);

    auto load_stage = [&](int l, int s) {
        const char* p = src + (size_t)l * step_bytes;
        uint32_t d = smem0 + (uint32_t)(s * 384);
        CP_ASYNC4(d,       p);
        CP_ASYNC4(d + 128, p + 1024);
        CP_ASYNC4(d + 256, p + 2048);
    };

#pragma unroll
    for (int s = 0; s < RSTAGES - 1; s++) {
        load_stage(s, s);
        CP_COMMIT();
    }

    __half2* Hp = reinterpret_cast<__half2*>(hout) + (size_t)b * (HID / 2) + hp;
    const size_t hstep = (size_t)BATCH * (HID / 2);

    float cx = 0.f, cy = 0.f, hx = 0.f, hy = 0.f;

    for (int l = 0; l < L_SEQ; l++) {
        CP_WAIT14();

        int s = l & (RSTAGES - 1);
        float2 u0 = __half22float2(sU[s][0][tid]);
        float2 u1 = __half22float2(sU[s][1][tid]);
        float2 u2 = __half22float2(sU[s][2][tid]);

        int ln = l + RSTAGES - 1;
        if (ln < L_SEQ) load_stage(ln, ln & (RSTAGES - 1));
        CP_COMMIT();

        float tfx = tanh_approx(fmaf(vf.x, cx, u1.x));
        float tfy = tanh_approx(fmaf(vf.y, cy, u1.y));
        float trx = tanh_approx(fmaf(vr.x, cx, u2.x));
        float try_ = tanh_approx(fmaf(vr.y, cy, u2.y));

        float fx = fmaf(tfx, 0.5f, 0.5f);
        float fy = fmaf(tfy, 0.5f, 0.5f);
        float rx = fmaf(trx, 0.5f, 0.5f);
        float ry = fmaf(try_, 0.5f, 0.5f);

        cx = fmaf(fx, cx - u0.x, u0.x);
        cy = fmaf(fy, cy - u0.y, u0.y);
        hx = rx * cx;
        hy = ry * cy;

        if (store_all) Hp[(size_t)l * hstep] = __floats2half2_rn(hx, hy);
    }

    if (!store_all) {
        hlast[b * HID + h]     = hx;
        hlast[b * HID + h + 1] = hy;
    }
}

// ---------------- final FC ----------------
__global__ void fc_kernel(const float* __restrict__ hl, const float* __restrict__ w,
                          const float* __restrict__ bias, float* __restrict__ out)
{
    int o = blockIdx.x;
    int b = blockIdx.y;
    float p = 0.f;
    for (int h = threadIdx.x; h < HID; h += 128)
        p += hl[b * HID + h] * w[o * HID + h];
#pragma unroll
    for (int s = 16; s > 0; s >>= 1) p += __shfl_down_sync(0xffffffffu, p, s);
    __shared__ float red[4];
    if ((threadIdx.x & 31) == 0) red[threadIdx.x >> 5] = p;
    __syncthreads();
    if (threadIdx.x == 0)
        out[b * OUTD + o] = red[0] + red[1] + red[2] + red[3] + bias[o];
}

// ---------------- launch ----------------
extern "C" void kernel_launch(void* const* d_in, const int* in_sizes, int n_in,
                              void* d_out, int out_size)
{
    const float* x   = (const float*)d_in[0];
    const float* W0  = (const float*)d_in[1];
    const float* v0  = (const float*)d_in[2];
    const float* b0  = (const float*)d_in[3];
    const float* W1  = (const float*)d_in[4];
    const float* v1  = (const float*)d_in[5];
    const float* b1  = (const float*)d_in[6];
    const float* fcw = (const float*)d_in[7];
    const float* fcb = (const float*)d_in[8];
    float* out = (float*)d_out;

    void *p_xh, *p_w0t, *p_w1t, *p_u, *p_h1, *p_h2l;
    cudaGetSymbolAddress(&p_xh,  g_xh);
    cudaGetSymbolAddress(&p_w0t, g_W0t);
    cudaGetSymbolAddress(&p_w1t, g_W1t);
    cudaGetSymbolAddress(&p_u,   g_U);
    cudaGetSymbolAddress(&p_h1,  g_h1);
    cudaGetSymbolAddress(&p_h2l, g_h2last);
    __half* xh  = (__half*)p_xh;
    __half* w0t = (__half*)p_w0t;
    __half* w1t = (__half*)p_w1t;
    __half* U   = (__half*)p_u;
    __half* h1  = (__half*)p_h1;
    float*  h2l = (float*)p_h2l;

    static int smem_set = 0;
    if (!smem_set) {
        cudaFuncSetAttribute(gemm_wide_kernel, cudaFuncAttributeMaxDynamicSharedMemorySize, WSMEM_B);
        smem_set = 1;
    }

    // 0: all prep in one launch
    prep_kernel<<<NB_F2H + NB_T0 + NB_T1, 256>>>(x, xh, W0, w0t, W1, w1t);

    // 1-2: layer 0
    gemm_kernel<<<dim3(N3H / 128, MROWS / 128), 256>>>(xh, w0t, b0, U, DIM);          // 1
    sru_rec_kernel<<<BATCH * 8, 32>>>(U, v0, h1, h2l, 1);                             // 2

    // 3-4: layer 1 (gemm2 at profile index 3)
    gemm_wide_kernel<<<dim3(N3H / 256, MROWS / 128), 512, WSMEM_B>>>(h1, w1t, b1, U, HID);  // 3 <- profiled
    sru_rec_kernel<<<BATCH * 8, 32>>>(U, v1, h1, h2l, 0);                             // 4

    // 5: head
    fc_kernel<<<dim3(OUTD, BATCH), 128>>>(h2l, fcw, fcb, out);                        // 5
}

// round 16
// speedup vs baseline: 1.0888x; 1.0888x over previous
#include <cuda_runtime.h>
#include <cuda_fp16.h>
#include <cstdint>
#include <cstddef>

#define L_SEQ 512
#define BATCH 128
#define DIM   128
#define HID   512
#define OUTD  5
#define N3H   1536
#define MROWS 65536  // L_SEQ*BATCH

// ---------------- scratch (static device globals; no allocations) ----------------
__device__ __align__(256) __half g_xh[MROWS * DIM];
__device__ __align__(256) __half g_W0t[N3H * DIM];
__device__ __align__(256) __half g_W1t[N3H * HID];
__device__ __align__(256) __half g_U[MROWS * N3H];
__device__ __align__(256) __half g_h1[MROWS * HID];
__device__ __align__(256) float  g_h2last[BATCH * HID];

// ---------------- helpers ----------------
__device__ __forceinline__ uint32_t smem_cast(const void* p)
{
    return (uint32_t)__cvta_generic_to_shared(p);
}

#define CP_ASYNC16(dst, src) asm volatile("cp.async.cg.shared.global [%0], [%1], 16;\n" :: "r"(dst), "l"(src))
#define CP_ASYNC4(dst, src)  asm volatile("cp.async.ca.shared.global [%0], [%1], 4;\n"  :: "r"(dst), "l"(src))
#define CP_COMMIT()          asm volatile("cp.async.commit_group;\n")
#define CP_WAIT1()           asm volatile("cp.async.wait_group 1;\n")
#define CP_WAIT14()          asm volatile("cp.async.wait_group 14;\n")

__device__ __forceinline__ float tanh_approx(float x)
{
    float t;
    asm("tanh.approx.f32 %0, %1;" : "=f"(t) : "f"(x));
    return t;
}

// ---------------- fused prep: x f2h + W0^T + W1^T (one launch) ----------------
#define NB_F2H (MROWS * DIM / 4 / 256)   // 8192
#define NB_T0  ((N3H / 32) * (DIM / 32)) // 192
#define NB_T1  ((N3H / 32) * (HID / 32)) // 768

__device__ __forceinline__ void trans_tile(const float* __restrict__ W, __half* __restrict__ Wt,
                                           int K, int N, int bx, int by, int tid)
{
    __shared__ float tile[32][33];
    int tx = tid & 31;
    int ty = tid >> 5;        // 0..7
    int nb = bx * 32;
    int kb = by * 32;
#pragma unroll
    for (int j = 0; j < 32; j += 8)
        tile[ty + j][tx] = W[(size_t)(kb + ty + j) * N + (nb + tx)];
    __syncthreads();
#pragma unroll
    for (int j = 0; j < 32; j += 8)
        Wt[(size_t)(nb + ty + j) * K + (kb + tx)] = __float2half(tile[tx][ty + j]);
}

__global__ void prep_kernel(const float* __restrict__ x, __half* __restrict__ xh,
                            const float* __restrict__ W0, __half* __restrict__ w0t,
                            const float* __restrict__ W1, __half* __restrict__ w1t)
{
    int bid = blockIdx.x;
    int tid = threadIdx.x;
    if (bid < NB_F2H) {
        int i = bid * 256 + tid;
        float4 v = reinterpret_cast<const float4*>(x)[i];
        __half2 lo = __floats2half2_rn(v.x, v.y);
        __half2 hi = __floats2half2_rn(v.z, v.w);
        uint2 pkt;
        pkt.x = *reinterpret_cast<uint32_t*>(&lo);
        pkt.y = *reinterpret_cast<uint32_t*>(&hi);
        reinterpret_cast<uint2*>(xh)[i] = pkt;
    } else if (bid < NB_F2H + NB_T0) {
        int b = bid - NB_F2H;
        trans_tile(W0, w0t, DIM, N3H, b % (N3H / 32), b / (N3H / 32), tid);
    } else {
        int b = bid - NB_F2H - NB_T0;
        trans_tile(W1, w1t, HID, N3H, b % (N3H / 32), b / (N3H / 32), tid);
    }
}

// ---------------- GEMM: 128x128 tile, 256 thr, 2 CTA/SM, 3-stage, SINGLE barrier/tile ----------------
#define LDSM4(R0, R1, R2, R3, ADDR) \
    asm volatile("ldmatrix.sync.aligned.m8n8.x4.shared.b16 {%0,%1,%2,%3}, [%4];" \
                 : "=r"(R0), "=r"(R1), "=r"(R2), "=r"(R3) : "r"(ADDR))

#define MMA16816(C0, C1, C2, C3, A0, A1, A2, A3, B0, B1)                              \
    asm volatile("mma.sync.aligned.m16n8k16.row.col.f32.f16.f16.f32 "                  \
                 "{%0,%1,%2,%3}, {%4,%5,%6,%7}, {%8,%9}, {%0,%1,%2,%3};"               \
                 : "+f"(C0), "+f"(C1), "+f"(C2), "+f"(C3)                              \
                 : "r"(A0), "r"(A1), "r"(A2), "r"(A3), "r"(B0), "r"(B1))

__device__ __forceinline__ int sw_gran(int row, int seg)
{
    return ((row >> 1) << 3) | ((((row & 1) << 2) | seg) ^ ((row >> 1) & 7));
}

// epilogue: cols [0,HID) raw; cols >= HID scaled 0.5 + 0.5*b[n-HID] (tanh-sigmoid form)
__global__ void __launch_bounds__(256, 2) gemm_kernel(
    const __half* __restrict__ A,
    const __half* __restrict__ B,
    const float* __restrict__ braw,   // raw SRU bias [2H]
    __half* __restrict__ C,
    int K)
{
    __shared__ __align__(1024) __half As[3][128 * 32];
    __shared__ __align__(1024) __half Bs[3][128 * 32];

    const int tid  = threadIdx.x;
    const int lane = tid & 31;
    const int wid  = tid >> 5;
    const int wm   = wid & 3;
    const int wn   = wid >> 2;
    const int m0   = blockIdx.y * 128;
    const int n0   = blockIdx.x * 128;
    const bool gc  = (n0 >= HID);
    const float s  = gc ? 0.5f : 1.f;

    auto load_tile = [&](int buf, int k0) {
        uint32_t as = smem_cast(&As[buf][0]);
        uint32_t bs = smem_cast(&Bs[buf][0]);
#pragma unroll
        for (int i = 0; i < 2; i++) {
            int lin = tid + i * 256;
            int row = lin >> 2;
            int seg = lin & 3;
            int g   = sw_gran(row, seg);
            CP_ASYNC16(as + g * 16, A + (size_t)(m0 + row) * K + (k0 + seg * 8));
            CP_ASYNC16(bs + g * 16, B + (size_t)(n0 + row) * K + (k0 + seg * 8));
        }
    };

    float acc[2][8][4];
#pragma unroll
    for (int mi = 0; mi < 2; mi++)
#pragma unroll
        for (int ni = 0; ni < 8; ni++)
#pragma unroll
            for (int j = 0; j < 4; j++) acc[mi][ni][j] = 0.f;

    const int T = K >> 5;
    load_tile(0, 0);
    CP_COMMIT();
    load_tile(1, 32);
    CP_COMMIT();

    const int a_row_base = wm * 32 + (lane & 15);
    const int a_koff     = lane >> 4;
    const int b_row_base = wn * 64 + (lane & 7) + ((lane & 16) ? 8 : 0);
    const int b_koff     = (lane >> 3) & 1;

    for (int t = 0; t < T; t++) {
        CP_WAIT1();            // this thread's loads for tile t complete
        __syncthreads();       // all threads' loads visible; stage (t-1)%3 fully consumed

        if (t + 2 < T) load_tile((t + 2) % 3, (t + 2) << 5);
        CP_COMMIT();           // uniform group count

        int cur = t % 3;
        uint32_t as = smem_cast(&As[cur][0]);
        uint32_t bs = smem_cast(&Bs[cur][0]);
#pragma unroll
        for (int kc = 0; kc < 2; kc++) {
            uint32_t a[2][4];
#pragma unroll
            for (int mi = 0; mi < 2; mi++) {
                int row = a_row_base + mi * 16;
                int seg = kc * 2 + a_koff;
                LDSM4(a[mi][0], a[mi][1], a[mi][2], a[mi][3], as + sw_gran(row, seg) * 16);
            }
            uint32_t bf[8][2];
#pragma unroll
            for (int nb = 0; nb < 4; nb++) {
                int row = b_row_base + nb * 16;
                int seg = kc * 2 + b_koff;
                LDSM4(bf[2 * nb][0], bf[2 * nb][1], bf[2 * nb + 1][0], bf[2 * nb + 1][1],
                      bs + sw_gran(row, seg) * 16);
            }
#pragma unroll
            for (int mi = 0; mi < 2; mi++)
#pragma unroll
                for (int ni = 0; ni < 8; ni++)
                    MMA16816(acc[mi][ni][0], acc[mi][ni][1], acc[mi][ni][2], acc[mi][ni][3],
                             a[mi][0], a[mi][1], a[mi][2], a[mi][3],
                             bf[ni][0], bf[ni][1]);
        }
        // NOTE: no bottom barrier — top barrier of iter t+1 provides the WAR protection
        // (writer of stage (t+3)%3 == (t)%3 issues only after that barrier).
    }

#pragma unroll
    for (int mi = 0; mi < 2; mi++) {
        int m = m0 + wm * 32 + mi * 16 + (lane >> 2);
#pragma unroll
        for (int ni = 0; ni < 8; ni++) {
            int n = n0 + wn * 64 + ni * 8 + (lane & 3) * 2;
            float2 bb;
            if (gc) {
                bb = *reinterpret_cast<const float2*>(braw + (n - HID));
                bb.x *= 0.5f; bb.y *= 0.5f;
            } else {
                bb.x = 0.f; bb.y = 0.f;
            }
            __half2 lo = __floats2half2_rn(fmaf(acc[mi][ni][0], s, bb.x),
                                           fmaf(acc[mi][ni][1], s, bb.y));
            __half2 hi = __floats2half2_rn(fmaf(acc[mi][ni][2], s, bb.x),
                                           fmaf(acc[mi][ni][3], s, bb.y));
            *reinterpret_cast<__half2*>(C + (size_t)m * N3H + n)       = lo;
            *reinterpret_cast<__half2*>(C + (size_t)(m + 8) * N3H + n) = hi;
        }
    }
}

// ---------------- SRU recurrence: per-thread cp.async ring, tanh sigmoid (PROVEN, DRAM-bound) ----------------
#define RSTAGES 16

__global__ void __launch_bounds__(32) sru_rec_kernel(
    const __half* __restrict__ U,    // u1/u2 cols pre-scaled 0.5 + 0.5*bias
    const float* __restrict__ v,
    __half* __restrict__ hout,
    float* __restrict__ hlast,
    int store_all)
{
    __shared__ __align__(128) __half2 sU[RSTAGES][3][32];   // 6 KB

    const int tid = threadIdx.x;
    const int b   = blockIdx.x >> 3;
    const int sub = blockIdx.x & 7;
    const int hp  = sub * 32 + tid;
    const int h   = hp << 1;

    float2 vf = *reinterpret_cast<const float2*>(v + h);
    float2 vr = *reinterpret_cast<const float2*>(v + HID + h);
    vf.x *= 0.5f; vf.y *= 0.5f;
    vr.x *= 0.5f; vr.y *= 0.5f;

    const char* src = (const char*)(U + (size_t)b * N3H + h);
    const size_t step_bytes = (size_t)BATCH * N3H * 2;
    const uint32_t smem0 = smem_cast(&sU[0][0][tid]);

    auto load_stage = [&](int l, int s) {
        const char* p = src + (size_t)l * step_bytes;
        uint32_t d = smem0 + (uint32_t)(s * 384);
        CP_ASYNC4(d,       p);
        CP_ASYNC4(d + 128, p + 1024);
        CP_ASYNC4(d + 256, p + 2048);
    };

#pragma unroll
    for (int s = 0; s < RSTAGES - 1; s++) {
        load_stage(s, s);
        CP_COMMIT();
    }

    __half2* Hp = reinterpret_cast<__half2*>(hout) + (size_t)b * (HID / 2) + hp;
    const size_t hstep = (size_t)BATCH * (HID / 2);

    float cx = 0.f, cy = 0.f, hx = 0.f, hy = 0.f;

    for (int l = 0; l < L_SEQ; l++) {
        CP_WAIT14();

        int s = l & (RSTAGES - 1);
        float2 u0 = __half22float2(sU[s][0][tid]);
        float2 u1 = __half22float2(sU[s][1][tid]);
        float2 u2 = __half22float2(sU[s][2][tid]);

        int ln = l + RSTAGES - 1;
        if (ln < L_SEQ) load_stage(ln, ln & (RSTAGES - 1));
        CP_COMMIT();

        float tfx = tanh_approx(fmaf(vf.x, cx, u1.x));
        float tfy = tanh_approx(fmaf(vf.y, cy, u1.y));
        float trx = tanh_approx(fmaf(vr.x, cx, u2.x));
        float try_ = tanh_approx(fmaf(vr.y, cy, u2.y));

        float fx = fmaf(tfx, 0.5f, 0.5f);
        float fy = fmaf(tfy, 0.5f, 0.5f);
        float rx = fmaf(trx, 0.5f, 0.5f);
        float ry = fmaf(try_, 0.5f, 0.5f);

        cx = fmaf(fx, cx - u0.x, u0.x);
        cy = fmaf(fy, cy - u0.y, u0.y);
        hx = rx * cx;
        hy = ry * cy;

        if (store_all) Hp[(size_t)l * hstep] = __floats2half2_rn(hx, hy);
    }

    if (!store_all) {
        hlast[b * HID + h]     = hx;
        hlast[b * HID + h + 1] = hy;
    }
}

// ---------------- final FC ----------------
__global__ void fc_kernel(const float* __restrict__ hl, const float* __restrict__ w,
                          const float* __restrict__ bias, float* __restrict__ out)
{
    int o = blockIdx.x;
    int b = blockIdx.y;
    float p = 0.f;
    for (int h = threadIdx.x; h < HID; h += 128)
        p += hl[b * HID + h] * w[o * HID + h];
#pragma unroll
    for (int s = 16; s > 0; s >>= 1) p += __shfl_down_sync(0xffffffffu, p, s);
    __shared__ float red[4];
    if ((threadIdx.x & 31) == 0) red[threadIdx.x >> 5] = p;
    __syncthreads();
    if (threadIdx.x == 0)
        out[b * OUTD + o] = red[0] + red[1] + red[2] + red[3] + bias[o];
}

// ---------------- launch ----------------
extern "C" void kernel_launch(void* const* d_in, const int* in_sizes, int n_in,
                              void* d_out, int out_size)
{
    const float* x   = (const float*)d_in[0];
    const float* W0  = (const float*)d_in[1];
    const float* v0  = (const float*)d_in[2];
    const float* b0  = (const float*)d_in[3];
    const float* W1  = (const float*)d_in[4];
    const float* v1  = (const float*)d_in[5];
    const float* b1  = (const float*)d_in[6];
    const float* fcw = (const float*)d_in[7];
    const float* fcb = (const float*)d_in[8];
    float* out = (float*)d_out;

    void *p_xh, *p_w0t, *p_w1t, *p_u, *p_h1, *p_h2l;
    cudaGetSymbolAddress(&p_xh,  g_xh);
    cudaGetSymbolAddress(&p_w0t, g_W0t);
    cudaGetSymbolAddress(&p_w1t, g_W1t);
    cudaGetSymbolAddress(&p_u,   g_U);
    cudaGetSymbolAddress(&p_h1,  g_h1);
    cudaGetSymbolAddress(&p_h2l, g_h2last);
    __half* xh  = (__half*)p_xh;
    __half* w0t = (__half*)p_w0t;
    __half* w1t = (__half*)p_w1t;
    __half* U   = (__half*)p_u;
    __half* h1  = (__half*)p_h1;
    float*  h2l = (float*)p_h2l;

    // 0: all prep in one launch
    prep_kernel<<<NB_F2H + NB_T0 + NB_T1, 256>>>(x, xh, W0, w0t, W1, w1t);

    // 1-2: layer 0
    gemm_kernel<<<dim3(N3H / 128, MROWS / 128), 256>>>(xh, w0t, b0, U, DIM);          // 1
    sru_rec_kernel<<<BATCH * 8, 32>>>(U, v0, h1, h2l, 1);                             // 2

    // 3-4: layer 1 (gemm2 at profile index 3)
    gemm_kernel<<<dim3(N3H / 128, MROWS / 128), 256>>>(h1, w1t, b1, U, HID);          // 3 <- profiled
    sru_rec_kernel<<<BATCH * 8, 32>>>(U, v1, h1, h2l, 0);                             // 4

    // 5: head
    fc_kernel<<<dim3(OUTD, BATCH), 128>>>(h2l, fcw, fcb, out);                        // 5
}